// round 7
// baseline (speedup 1.0000x reference)
#include <cuda_runtime.h>
#include <cuda_fp16.h>
#include <cstdint>
#include <math.h>

// Problem dims
#define T_TOK 512
#define DDIM 1024
#define FDIM 4096
#define NEXP 8
#define RLORA 16
#define NPAIR 1024
#define SCALING 2.0f
#define EPS_RMS 1e-6f
#define GSZ 32
#define MAXG 40

// ---------------- scratch (device globals) ----------------------------------
__device__ float g_t[T_TOK * DDIM];
__device__ __half g_th[T_TOK * DDIM];
__device__ __half g_w1h[FDIM * DDIM], g_w3h[FDIM * DDIM];
__device__ __half g_w2h[DDIM * FDIM];
__device__ __half g_a1h[NEXP * RLORA * DDIM], g_a3h[NEXP * RLORA * DDIM];
__device__ __half g_a2h[NEXP * RLORA * FDIM];
__device__ __half g_acth[NPAIR * FDIM];
__device__ __half g_ch[T_TOK * FDIM];
__device__ float g_base1[T_TOK * FDIM];
__device__ float g_base3[T_TOK * FDIM];
__device__ float g_etrup[NPAIR * 2 * RLORA];
__device__ float g_etr2[NPAIR * RLORA];
__device__ int   g_topi[NPAIR];
__device__ float g_topw[NPAIR];
__device__ int   g_sorted[NPAIR];
__device__ int   g_gstart[MAXG], g_glen[MAXG], g_gexp[MAXG];
__device__ int   g_ngroups;

// ---------------- helpers ----------------------------------------------------
__device__ __forceinline__ uint32_t smem_u32(const void* p) {
    return (uint32_t)__cvta_generic_to_shared(p);
}
__device__ __forceinline__ uint32_t packh(float a, float b) {
    return ((uint32_t)__half_as_ushort(__float2half_rn(b)) << 16) |
           __half_as_ushort(__float2half_rn(a));
}
__device__ __forceinline__ float2 h22f2(uint32_t u) {
    return __half22float2(*(__half2*)&u);
}

__device__ __forceinline__ void ldsm_x4(uint32_t (&r)[4], uint32_t a) {
    asm volatile("ldmatrix.sync.aligned.m8n8.x4.shared.b16 {%0,%1,%2,%3}, [%4];"
                 : "=r"(r[0]), "=r"(r[1]), "=r"(r[2]), "=r"(r[3]) : "r"(a));
}
__device__ __forceinline__ void ldsm_x2(uint32_t (&r)[2], uint32_t a) {
    asm volatile("ldmatrix.sync.aligned.m8n8.x2.shared.b16 {%0,%1}, [%2];"
                 : "=r"(r[0]), "=r"(r[1]) : "r"(a));
}
__device__ __forceinline__ void mma_f16(float (&c)[4], const uint32_t (&a)[4],
                                        const uint32_t (&b)[2]) {
    asm volatile(
        "mma.sync.aligned.m16n8k16.row.col.f32.f16.f16.f32 "
        "{%0,%1,%2,%3}, {%4,%5,%6,%7}, {%8,%9}, {%0,%1,%2,%3};"
        : "+f"(c[0]), "+f"(c[1]), "+f"(c[2]), "+f"(c[3])
        : "r"(a[0]), "r"(a[1]), "r"(a[2]), "r"(a[3]), "r"(b[0]), "r"(b[1]));
}
__device__ __forceinline__ void cp16(uint32_t dst, const void* src) {
    asm volatile("cp.async.cg.shared.global [%0], [%1], 16;" :: "r"(dst), "l"(src));
}
__device__ __forceinline__ void cp_commit() {
    asm volatile("cp.async.commit_group;" ::: "memory");
}
__device__ __forceinline__ void cp_wait0() {
    asm volatile("cp.async.wait_group 0;" ::: "memory");
}
__device__ __forceinline__ void cp_wait1() {
    asm volatile("cp.async.wait_group 1;" ::: "memory");
}
__device__ __forceinline__ void cp_wait2() {
    asm volatile("cp.async.wait_group 2;" ::: "memory");
}

// load ROWS x 64 fp16 tile into SW128-swizzled smem via cp.async
template <int ROWS, int THREADS>
__device__ __forceinline__ void load_tile(uint32_t sdst, const __half* g,
                                          int ld, int tid) {
#pragma unroll
    for (int i = 0; i < ROWS * 8 / THREADS; ++i) {
        int idx = i * THREADS + tid;
        int row = idx >> 3, ch = idx & 7;
        uint32_t dst = sdst + row * 128 + ((ch * 16) ^ ((row & 7) << 4));
        cp16(dst, g + (size_t)row * ld + ch * 8);
    }
}

// one K-chunk (64) of single-pass fp16 mma: acc += A*B
template <int MT, int NT>
__device__ __forceinline__ void compute_chunk1(uint32_t sA, uint32_t sB,
                                               int warpRow, int warpCol, int lane,
                                               float (&acc)[MT][NT][4]) {
    int mi = lane >> 3;
    int arow = warpRow + ((mi & 1) << 3) + (lane & 7);
    uint32_t axor = (uint32_t)((arow & 7) << 4);
    uint32_t aoff = (uint32_t)arow * 128;
    int akb = (mi >> 1) << 4;
    int brow = warpCol + (lane & 7);
    int bi = (lane >> 3) & 1;
    uint32_t bxor = (uint32_t)((brow & 7) << 4);
    uint32_t boff = (uint32_t)brow * 128;
    int bkb = bi << 4;
#pragma unroll
    for (int ks = 0; ks < 4; ++ks) {
        uint32_t af[MT][4], bh[NT][2];
        uint32_t ak = (uint32_t)((ks * 32 + akb) ^ axor);
        uint32_t bk = (uint32_t)((ks * 32 + bkb) ^ bxor);
#pragma unroll
        for (int i = 0; i < MT; ++i) ldsm_x4(af[i], sA + aoff + i * 2048 + ak);
#pragma unroll
        for (int j = 0; j < NT; ++j) ldsm_x2(bh[j], sB + boff + j * 1024 + bk);
#pragma unroll
        for (int i = 0; i < MT; ++i)
#pragma unroll
            for (int j = 0; j < NT; ++j) mma_f16(acc[i][j], af[i], bh[j]);
    }
}

// ---------------- kernel: fp32 -> fp16 conversions (all weights) -------------
#define N_W (FDIM * DDIM / 4)
#define N_A1 (NEXP * RLORA * DDIM / 4)
#define N_A2 (NEXP * RLORA * FDIM / 4)
__global__ void cvt_kernel(const float* __restrict__ w1, const float* __restrict__ w3,
                           const float* __restrict__ w2, const float* __restrict__ a1,
                           const float* __restrict__ a3, const float* __restrict__ a2) {
    const int total = 3 * N_W + 2 * N_A1 + N_A2;
    for (int i = blockIdx.x * blockDim.x + threadIdx.x; i < total;
         i += gridDim.x * blockDim.x) {
        int j = i;
        const float4* s;
        uint2* d;
        if (j < N_W)                    { s = (const float4*)w1; d = (uint2*)g_w1h; }
        else if ((j -= N_W) < N_W)      { s = (const float4*)w3; d = (uint2*)g_w3h; }
        else if ((j -= N_W) < N_W)      { s = (const float4*)w2; d = (uint2*)g_w2h; }
        else if ((j -= N_W) < N_A1)     { s = (const float4*)a1; d = (uint2*)g_a1h; }
        else if ((j -= N_A1) < N_A1)    { s = (const float4*)a3; d = (uint2*)g_a3h; }
        else { j -= N_A1;                 s = (const float4*)a2; d = (uint2*)g_a2h; }
        float4 v = s[j];
        uint2 o;
        o.x = packh(v.x, v.y);
        o.y = packh(v.z, v.w);
        d[j] = o;
    }
}

// ---------------- kernel: fused RMSNorm + router (+ etr2 zero) ---------------
__global__ void rmsnorm_router_kernel(const float* __restrict__ x,
                                      const float* __restrict__ nw,
                                      const float* __restrict__ gw) {
    int tok = blockIdx.x;
    int tid = threadIdx.x;
    if (tid < 32) g_etr2[tok * 32 + tid] = 0.f;
    float4 v = ((const float4*)(x + (size_t)tok * DDIM))[tid];
    float ss = v.x * v.x + v.y * v.y + v.z * v.z + v.w * v.w;
#pragma unroll
    for (int o = 16; o; o >>= 1) ss += __shfl_xor_sync(0xffffffffu, ss, o);
    __shared__ float red[8];
    if ((tid & 31) == 0) red[tid >> 5] = ss;
    __syncthreads();
    float tot = 0.f;
#pragma unroll
    for (int i = 0; i < 8; ++i) tot += red[i];
    float sc = rsqrtf(tot / (float)DDIM + EPS_RMS);
    float4 w = ((const float4*)nw)[tid];
    float4 o = make_float4(v.x * sc * w.x, v.y * sc * w.y, v.z * sc * w.z,
                           v.w * sc * w.w);
    ((float4*)(g_t + (size_t)tok * DDIM))[tid] = o;
    uint2 h;
    h.x = packh(o.x, o.y);
    h.y = packh(o.z, o.w);
    ((uint2*)g_th)[tok * 256 + tid] = h;

    float r[NEXP];
#pragma unroll
    for (int e = 0; e < NEXP; ++e) {
        float4 gv = ((const float4*)gw)[e * 256 + tid];
        r[e] = o.x * gv.x + o.y * gv.y + o.z * gv.z + o.w * gv.w;
    }
#pragma unroll
    for (int e = 0; e < NEXP; ++e) {
#pragma unroll
        for (int off = 16; off; off >>= 1)
            r[e] += __shfl_xor_sync(0xffffffffu, r[e], off);
    }
    __shared__ float lg[8][NEXP];
    if ((tid & 31) == 0) {
#pragma unroll
        for (int e = 0; e < NEXP; ++e) lg[tid >> 5][e] = r[e];
    }
    __syncthreads();
    if (tid == 0) {
        float s8[NEXP];
#pragma unroll
        for (int e = 0; e < NEXP; ++e) {
            float t = 0.f;
#pragma unroll
            for (int wgi = 0; wgi < 8; ++wgi) t += lg[wgi][e];
            s8[e] = t;
        }
        int i0 = 0;
#pragma unroll
        for (int i = 1; i < NEXP; ++i) if (s8[i] > s8[i0]) i0 = i;
        int i1 = (i0 == 0) ? 1 : 0;
#pragma unroll
        for (int i = 0; i < NEXP; ++i) if (i != i0 && s8[i] > s8[i1]) i1 = i;
        float e1 = expf(s8[i1] - s8[i0]);
        float inv = 1.f / (1.f + e1);
        g_topi[tok * 2 + 0] = i0;
        g_topi[tok * 2 + 1] = i1;
        g_topw[tok * 2 + 0] = inv;
        g_topw[tok * 2 + 1] = e1 * inv;
    }
}

// ---------------- kernel: expert-sort pairs ----------------------------------
__global__ void sort_kernel() {
    __shared__ int cnt[NEXP], ofs[NEXP + 1], cur[NEXP];
    int tid = threadIdx.x;
    if (tid < NEXP) cnt[tid] = 0;
    __syncthreads();
    for (int p = tid; p < NPAIR; p += 256) atomicAdd(&cnt[g_topi[p]], 1);
    __syncthreads();
    if (tid == 0) {
        ofs[0] = 0;
        for (int e = 0; e < NEXP; ++e) { ofs[e + 1] = ofs[e] + cnt[e]; cur[e] = ofs[e]; }
        int ng = 0;
        for (int e = 0; e < NEXP; ++e)
            for (int s = 0; s < cnt[e]; s += GSZ) {
                g_gstart[ng] = ofs[e] + s;
                g_glen[ng] = min(GSZ, cnt[e] - s);
                g_gexp[ng] = e;
                ng++;
            }
        g_ngroups = ng;
    }
    __syncthreads();
    for (int p = tid; p < NPAIR; p += 256) {
        int pos = atomicAdd(&cur[g_topi[p]], 1);
        g_sorted[pos] = p;
    }
}

// ---------------- kernel: up GEMMs (128x128 tile, 1-pass fp16, 3 stages) -----
#define UP_TA (128 * 64 * 2)
#define UP_TB (128 * 64 * 2)
#define UP_STAGE (UP_TA + UP_TB)
__global__ __launch_bounds__(256, 2) void up_mma_kernel() {
    extern __shared__ __align__(128) char smem[];
    const int tid = threadIdx.x;
    const int wid = tid >> 5, lane = tid & 31;
    const int warpRow = (wid >> 1) * 32, warpCol = (wid & 1) * 64;
    uint32_t sb = smem_u32(smem);

    const __half* Ah = g_th + (size_t)blockIdx.y * 128 * DDIM;
    const __half* Bh = (blockIdx.z ? g_w3h : g_w1h) + (size_t)blockIdx.x * 128 * DDIM;

    float acc[2][8][4] = {};
    const int NC = DDIM / 64;  // 16

    {
        load_tile<128, 256>(sb, Ah, DDIM, tid);
        load_tile<128, 256>(sb + UP_TA, Bh, DDIM, tid);
        cp_commit();
        uint32_t s1 = sb + UP_STAGE;
        load_tile<128, 256>(s1, Ah + 64, DDIM, tid);
        load_tile<128, 256>(s1 + UP_TA, Bh + 64, DDIM, tid);
        cp_commit();
    }
    for (int c = 0; c < NC; ++c) {
        if (c + 2 < NC) {
            uint32_t s2 = sb + ((c + 2) % 3) * UP_STAGE;
            load_tile<128, 256>(s2, Ah + (c + 2) * 64, DDIM, tid);
            load_tile<128, 256>(s2 + UP_TA, Bh + (c + 2) * 64, DDIM, tid);
            cp_commit();
            cp_wait2();
        } else if (c + 1 < NC) {
            cp_wait1();
        } else {
            cp_wait0();
        }
        __syncthreads();
        uint32_t s = sb + (c % 3) * UP_STAGE;
        compute_chunk1<2, 8>(s, s + UP_TA, warpRow, warpCol, lane, acc);
        __syncthreads();
    }

    float* dst = blockIdx.z ? g_base3 : g_base1;
    int grp = lane >> 2, q = lane & 3;
#pragma unroll
    for (int i = 0; i < 2; ++i) {
        int r0 = blockIdx.y * 128 + warpRow + i * 16 + grp;
#pragma unroll
        for (int j = 0; j < 8; ++j) {
            int col = blockIdx.x * 128 + warpCol + j * 8 + q * 2;
            *(float2*)(dst + (size_t)r0 * FDIM + col) =
                make_float2(acc[i][j][0], acc[i][j][1]);
            *(float2*)(dst + (size_t)(r0 + 8) * FDIM + col) =
                make_float2(acc[i][j][2], acc[i][j][3]);
        }
    }
}

// ---------------- kernel: grouped up LoRA rank projections -------------------
// grid (MAXG). a1+a3 rows for the group's expert cached in smem.
#define AUP 258
__global__ __launch_bounds__(256) void etr_up_group_kernel() {
    int gi = blockIdx.x;
    if (gi >= g_ngroups) return;
    int e = g_gexp[gi], start = g_gstart[gi], len = g_glen[gi];
    int tid = threadIdx.x;
    extern __shared__ __align__(16) uint2 sa[];  // [32][AUP]
    __shared__ int sp[GSZ];
    if (tid < len) sp[tid] = g_sorted[start + tid];
    const uint2* a1g = (const uint2*)(g_a1h + (size_t)e * RLORA * DDIM);
    const uint2* a3g = (const uint2*)(g_a3h + (size_t)e * RLORA * DDIM);
    for (int i = tid; i < 16 * 256; i += 256) {
        int r = i >> 8, d = i & 255;
        sa[r * AUP + d] = a1g[r * 256 + d];
        sa[(16 + r) * AUP + d] = a3g[r * 256 + d];
    }
    __syncthreads();
    int k = tid >> 3, rr = tid & 7;
    if (k < len) {
        int p = sp[k], tok = p >> 1;
        const float4* trow = (const float4*)(g_t + (size_t)tok * DDIM);
        float s0 = 0.f, s1 = 0.f, s2 = 0.f, s3 = 0.f;
        const uint2* r0 = sa + (rr) * AUP;
        const uint2* r1 = sa + (rr + 8) * AUP;
        const uint2* r2 = sa + (rr + 16) * AUP;
        const uint2* r3 = sa + (rr + 24) * AUP;
#pragma unroll 4
        for (int d = 0; d < 256; ++d) {
            float4 u = trow[d];
            uint2 v0 = r0[d], v1 = r1[d], v2 = r2[d], v3 = r3[d];
            float2 a01, a23;
            a01 = h22f2(v0.x); a23 = h22f2(v0.y);
            s0 += u.x * a01.x + u.y * a01.y + u.z * a23.x + u.w * a23.y;
            a01 = h22f2(v1.x); a23 = h22f2(v1.y);
            s1 += u.x * a01.x + u.y * a01.y + u.z * a23.x + u.w * a23.y;
            a01 = h22f2(v2.x); a23 = h22f2(v2.y);
            s2 += u.x * a01.x + u.y * a01.y + u.z * a23.x + u.w * a23.y;
            a01 = h22f2(v3.x); a23 = h22f2(v3.y);
            s3 += u.x * a01.x + u.y * a01.y + u.z * a23.x + u.w * a23.y;
        }
        g_etrup[p * 32 + rr]      = s0;
        g_etrup[p * 32 + rr + 8]  = s1;
        g_etrup[p * 32 + rr + 16] = s2;
        g_etrup[p * 32 + rr + 24] = s3;
    }
}

// ---------------- kernel: grouped LoRA expand + SwiGLU (fp16 act) ------------
__global__ __launch_bounds__(256) void act_group_kernel(const float* __restrict__ b1w,
                                                        const float* __restrict__ b3w) {
    int gi = blockIdx.x;
    if (gi >= g_ngroups) return;
    int e = g_gexp[gi], start = g_gstart[gi], len = g_glen[gi];
    int tid = threadIdx.x;
    int f0 = blockIdx.y * 512 + tid * 2;
    __shared__ float sg[GSZ][32];
    __shared__ int sp[GSZ];
    for (int i = tid; i < len * 32; i += 256) {
        int k = i >> 5;
        sg[k][i & 31] = g_etrup[g_sorted[start + k] * 32 + (i & 31)];
    }
    if (tid < len) sp[tid] = g_sorted[start + tid];
    __syncthreads();

    float b1r[2][16], b3r[2][16];
#pragma unroll
    for (int fi = 0; fi < 2; ++fi) {
        const float4* q1 = (const float4*)(b1w + ((size_t)e * FDIM + f0 + fi) * RLORA);
        const float4* q3 = (const float4*)(b3w + ((size_t)e * FDIM + f0 + fi) * RLORA);
#pragma unroll
        for (int i = 0; i < 4; ++i) {
            float4 v1 = q1[i], v3 = q3[i];
            b1r[fi][i * 4 + 0] = v1.x; b1r[fi][i * 4 + 1] = v1.y;
            b1r[fi][i * 4 + 2] = v1.z; b1r[fi][i * 4 + 3] = v1.w;
            b3r[fi][i * 4 + 0] = v3.x; b3r[fi][i * 4 + 1] = v3.y;
            b3r[fi][i * 4 + 2] = v3.z; b3r[fi][i * 4 + 3] = v3.w;
        }
    }
    for (int k = 0; k < len; ++k) {
        int p = sp[k], tok = p >> 1;
        float2 bs1 = *(const float2*)(g_base1 + (size_t)tok * FDIM + f0);
        float2 bs3 = *(const float2*)(g_base3 + (size_t)tok * FDIM + f0);
        float hv[2];
#pragma unroll
        for (int fi = 0; fi < 2; ++fi) {
            float l1 = 0.f, l3 = 0.f;
#pragma unroll
            for (int r = 0; r < 16; ++r) {
                l1 += b1r[fi][r] * sg[k][r];
                l3 += b3r[fi][r] * sg[k][16 + r];
            }
            float h1 = (fi ? bs1.y : bs1.x) + SCALING * l1;
            float h3 = (fi ? bs3.y : bs3.x) + SCALING * l3;
            hv[fi] = (h1 / (1.f + expf(-h1))) * h3;
        }
        ((uint32_t*)g_acth)[((size_t)p * FDIM + f0) >> 1] = packh(hv[0], hv[1]);
    }
}

// ---------------- kernel: grouped down LoRA rank projection ------------------
#define A2PITCH 516
__global__ __launch_bounds__(256) void etr2_group_kernel() {
    int gi = blockIdx.x;
    if (gi >= g_ngroups) return;
    int e = g_gexp[gi], start = g_gstart[gi], len = g_glen[gi];
    int cidx = blockIdx.y;
    int tid = threadIdx.x;
    extern __shared__ __align__(16) uint32_t sm[];
    uint32_t* sa2 = sm;                       // [16][A2PITCH]
    uint32_t* sact = sm + 16 * A2PITCH;       // [32][A2PITCH]
    __shared__ int sp[GSZ];
    if (tid < len) sp[tid] = g_sorted[start + tid];
    __syncthreads();
    const uint32_t* a2g = (const uint32_t*)g_a2h;
    for (int i = tid; i < 16 * 512; i += 256) {
        int r = i >> 9, d = i & 511;
        sa2[r * A2PITCH + d] = a2g[((size_t)(e * RLORA + r) << 11) + (cidx << 9) + d];
    }
    const uint32_t* actg = (const uint32_t*)g_acth;
    for (int i = tid; i < len * 512; i += 256) {
        int k = i >> 9, d = i & 511;
        sact[k * A2PITCH + d] = actg[((size_t)sp[k] << 11) + (cidx << 9) + d];
    }
    __syncthreads();
    int k = tid >> 3, rr = tid & 7;
    if (k < len) {
        float a0 = 0.f, a1 = 0.f;
        const uint32_t* ar = sact + k * A2PITCH;
        const uint32_t* b0 = sa2 + rr * A2PITCH;
        const uint32_t* b1 = sa2 + (rr + 8) * A2PITCH;
#pragma unroll 4
        for (int d = 0; d < 512; ++d) {
            float2 av = h22f2(ar[d]);
            float2 v0 = h22f2(b0[d]);
            float2 v1 = h22f2(b1[d]);
            a0 += av.x * v0.x + av.y * v0.y;
            a1 += av.x * v1.x + av.y * v1.y;
        }
        int p = sp[k];
        float sc = SCALING * g_topw[p];
        atomicAdd(&g_etr2[p * RLORA + rr], a0 * sc);
        atomicAdd(&g_etr2[p * RLORA + rr + 8], a1 * sc);
    }
}

// ---------------- kernel: weighted pair combine (single fp16) ----------------
__global__ void combine_kernel() {
    int tok = blockIdx.x;
    int f0 = (blockIdx.y * 256 + threadIdx.x) * 4;
    float w0 = g_topw[tok * 2], w1 = g_topw[tok * 2 + 1];
    size_t i0 = ((size_t)(2 * tok) * FDIM + f0) >> 2;
    size_t i1 = i0 + (FDIM >> 2);
    uint2 u0 = ((const uint2*)g_acth)[i0];
    uint2 u1 = ((const uint2*)g_acth)[i1];
    float2 a01 = h22f2(u0.x), a23 = h22f2(u0.y);
    float2 b01 = h22f2(u1.x), b23 = h22f2(u1.y);
    uint2 h;
    h.x = packh(w0 * a01.x + w1 * b01.x, w0 * a01.y + w1 * b01.y);
    h.y = packh(w0 * a23.x + w1 * b23.x, w0 * a23.y + w1 * b23.y);
    ((uint2*)g_ch)[((size_t)tok * FDIM + f0) >> 2] = h;
}

// ---------------- kernel: down GEMM (64x128, splitK=2, 1-pass, 3 stages) -----
#define DN_TA (64 * 64 * 2)
#define DN_TB (128 * 64 * 2)
#define DN_STAGE (DN_TA + DN_TB)
__global__ __launch_bounds__(256, 2) void down_mma_kernel(const float* __restrict__ B2,
                                                          float* __restrict__ Out) {
    extern __shared__ __align__(128) char smem[];
    const int tid = threadIdx.x;
    const int wid = tid >> 5, lane = tid & 31;
    const int warpRow = (wid >> 2) * 32, warpCol = (wid & 3) * 32;
    uint32_t sb = smem_u32(smem);
    const int kOff = blockIdx.z * (FDIM / 2);

    const __half* Ah = g_ch + (size_t)blockIdx.y * 64 * FDIM + kOff;
    const __half* Bh = g_w2h + (size_t)blockIdx.x * 128 * FDIM + kOff;

    float acc[2][4][4] = {};
    const int NC = (FDIM / 2) / 64;  // 32

    {
        load_tile<64, 256>(sb, Ah, FDIM, tid);
        load_tile<128, 256>(sb + DN_TA, Bh, FDIM, tid);
        cp_commit();
        uint32_t s1 = sb + DN_STAGE;
        load_tile<64, 256>(s1, Ah + 64, FDIM, tid);
        load_tile<128, 256>(s1 + DN_TA, Bh + 64, FDIM, tid);
        cp_commit();
    }
    for (int c = 0; c < NC; ++c) {
        if (c + 2 < NC) {
            uint32_t s2 = sb + ((c + 2) % 3) * DN_STAGE;
            load_tile<64, 256>(s2, Ah + (c + 2) * 64, FDIM, tid);
            load_tile<128, 256>(s2 + DN_TA, Bh + (c + 2) * 64, FDIM, tid);
            cp_commit();
            cp_wait2();
        } else if (c + 1 < NC) {
            cp_wait1();
        } else {
            cp_wait0();
        }
        __syncthreads();
        uint32_t s = sb + (c % 3) * DN_STAGE;
        compute_chunk1<2, 4>(s, s + DN_TA, warpRow, warpCol, lane, acc);
        __syncthreads();
    }

    int grp = lane >> 2, q = lane & 3;
#pragma unroll
    for (int i = 0; i < 2; ++i) {
#pragma unroll
        for (int half = 0; half < 2; ++half) {
            int t = blockIdx.y * 64 + warpRow + i * 16 + half * 8 + grp;
            if (blockIdx.z == 0) {
                int p0 = 2 * t, p1 = 2 * t + 1;
                int e0 = g_topi[p0], e1 = g_topi[p1];
                float er0[16], er1[16];
                const float4* q0 = (const float4*)(g_etr2 + p0 * RLORA);
                const float4* q1v = (const float4*)(g_etr2 + p1 * RLORA);
#pragma unroll
                for (int kk = 0; kk < 4; ++kk) {
                    float4 a = q0[kk], b = q1v[kk];
                    er0[kk * 4 + 0] = a.x; er0[kk * 4 + 1] = a.y;
                    er0[kk * 4 + 2] = a.z; er0[kk * 4 + 3] = a.w;
                    er1[kk * 4 + 0] = b.x; er1[kk * 4 + 1] = b.y;
                    er1[kk * 4 + 2] = b.z; er1[kk * 4 + 3] = b.w;
                }
#pragma unroll
                for (int j = 0; j < 4; ++j) {
#pragma unroll
                    for (int c2 = 0; c2 < 2; ++c2) {
                        int d = blockIdx.x * 128 + warpCol + j * 8 + q * 2 + c2;
                        const float4* r0p =
                            (const float4*)(B2 + ((size_t)e0 * DDIM + d) * RLORA);
                        const float4* r1p =
                            (const float4*)(B2 + ((size_t)e1 * DDIM + d) * RLORA);
                        float dot = 0.f;
#pragma unroll
                        for (int kk = 0; kk < 4; ++kk) {
                            float4 b0 = r0p[kk], b1v = r1p[kk];
                            dot += b0.x * er0[kk * 4 + 0] + b0.y * er0[kk * 4 + 1] +
                                   b0.z * er0[kk * 4 + 2] + b0.w * er0[kk * 4 + 3];
                            dot += b1v.x * er1[kk * 4 + 0] + b1v.y * er1[kk * 4 + 1] +
                                   b1v.z * er1[kk * 4 + 2] + b1v.w * er1[kk * 4 + 3];
                        }
                        atomicAdd(&Out[(size_t)t * DDIM + d],
                                  acc[i][j][half * 2 + c2] + dot);
                    }
                }
            } else {
#pragma unroll
                for (int j = 0; j < 4; ++j) {
#pragma unroll
                    for (int c2 = 0; c2 < 2; ++c2) {
                        int d = blockIdx.x * 128 + warpCol + j * 8 + q * 2 + c2;
                        atomicAdd(&Out[(size_t)t * DDIM + d], acc[i][j][half * 2 + c2]);
                    }
                }
            }
        }
    }
}

// ---------------- launcher ---------------------------------------------------
extern "C" void kernel_launch(void* const* d_in, const int* in_sizes, int n_in,
                              void* d_out, int out_size) {
    const float* x      = (const float*)d_in[0];
    const float* norm_w = (const float*)d_in[1];
    const float* w1     = (const float*)d_in[2];
    const float* w3     = (const float*)d_in[3];
    const float* w2     = (const float*)d_in[4];
    const float* gate_w = (const float*)d_in[5];
    const float* a1     = (const float*)d_in[6];
    const float* b1     = (const float*)d_in[7];
    const float* a3     = (const float*)d_in[8];
    const float* b3     = (const float*)d_in[9];
    const float* a2     = (const float*)d_in[10];
    const float* b2     = (const float*)d_in[11];
    float* out = (float*)d_out;

    const int ETR2_SMEM = (16 + 32) * A2PITCH * 4;   // 99072
    const int ETRUP_SMEM = 32 * AUP * 8;             // 66048
    cudaFuncSetAttribute(up_mma_kernel,
                         cudaFuncAttributeMaxDynamicSharedMemorySize, 3 * UP_STAGE);
    cudaFuncSetAttribute(down_mma_kernel,
                         cudaFuncAttributeMaxDynamicSharedMemorySize, 3 * DN_STAGE);
    cudaFuncSetAttribute(etr2_group_kernel,
                         cudaFuncAttributeMaxDynamicSharedMemorySize, ETR2_SMEM);
    cudaFuncSetAttribute(etr_up_group_kernel,
                         cudaFuncAttributeMaxDynamicSharedMemorySize, ETRUP_SMEM);

    cudaMemsetAsync(d_out, 0, (size_t)out_size * sizeof(float));
    cvt_kernel<<<1024, 256>>>(w1, w3, w2, a1, a3, a2);
    rmsnorm_router_kernel<<<T_TOK, 256>>>(x, norm_w, gate_w);
    sort_kernel<<<1, 256>>>();
    etr_up_group_kernel<<<MAXG, 256, ETRUP_SMEM>>>();
    up_mma_kernel<<<dim3(FDIM / 128, T_TOK / 128, 2), 256, 3 * UP_STAGE>>>();
    act_group_kernel<<<dim3(MAXG, 8), 256>>>(b1, b3);
    etr2_group_kernel<<<dim3(MAXG, 4), 256, ETR2_SMEM>>>();
    combine_kernel<<<dim3(T_TOK, 4), 256>>>();
    down_mma_kernel<<<dim3(DDIM / 128, T_TOK / 64, 2), 256, 3 * DN_STAGE>>>(b2, out);
}

// round 8
// speedup vs baseline: 1.1412x; 1.1412x over previous
#include <cuda_runtime.h>
#include <cuda_fp16.h>
#include <cstdint>
#include <math.h>

// Problem dims
#define T_TOK 512
#define DDIM 1024
#define FDIM 4096
#define NEXP 8
#define RLORA 16
#define NPAIR 1024
#define SCALING 2.0f
#define EPS_RMS 1e-6f
#define GSZ 32
#define MAXG 40

// ---------------- scratch (device globals) ----------------------------------
__device__ float g_t[T_TOK * DDIM];
__device__ __half g_th[T_TOK * DDIM];
__device__ __half g_w1h[FDIM * DDIM], g_w3h[FDIM * DDIM];
__device__ __half g_w2h[DDIM * FDIM];
__device__ __half g_aUh[2 * NEXP * RLORA * DDIM];   // a1 (128 rows) ++ a3 (128 rows)
__device__ __half g_a2h[NEXP * RLORA * FDIM];
__device__ __half g_acth[NPAIR * FDIM];
__device__ __half g_ch[T_TOK * FDIM];
__device__ float g_base1[T_TOK * FDIM];
__device__ float g_base3[T_TOK * FDIM];
__device__ float g_etrupd[T_TOK * 256];             // dense t@[a1;a3]^T
__device__ float g_etr2[NPAIR * RLORA];
__device__ int   g_topi[NPAIR];
__device__ float g_topw[NPAIR];
__device__ int   g_sorted[NPAIR];
__device__ int   g_gstart[MAXG], g_glen[MAXG], g_gexp[MAXG];
__device__ int   g_ngroups;

// ---------------- helpers ----------------------------------------------------
__device__ __forceinline__ uint32_t smem_u32(const void* p) {
    return (uint32_t)__cvta_generic_to_shared(p);
}
__device__ __forceinline__ uint32_t packh(float a, float b) {
    return ((uint32_t)__half_as_ushort(__float2half_rn(b)) << 16) |
           __half_as_ushort(__float2half_rn(a));
}
__device__ __forceinline__ float2 h22f2(uint32_t u) {
    return __half22float2(*(__half2*)&u);
}

__device__ __forceinline__ void ldsm_x4(uint32_t (&r)[4], uint32_t a) {
    asm volatile("ldmatrix.sync.aligned.m8n8.x4.shared.b16 {%0,%1,%2,%3}, [%4];"
                 : "=r"(r[0]), "=r"(r[1]), "=r"(r[2]), "=r"(r[3]) : "r"(a));
}
__device__ __forceinline__ void ldsm_x2(uint32_t (&r)[2], uint32_t a) {
    asm volatile("ldmatrix.sync.aligned.m8n8.x2.shared.b16 {%0,%1}, [%2];"
                 : "=r"(r[0]), "=r"(r[1]) : "r"(a));
}
__device__ __forceinline__ void mma_f16(float (&c)[4], const uint32_t (&a)[4],
                                        const uint32_t (&b)[2]) {
    asm volatile(
        "mma.sync.aligned.m16n8k16.row.col.f32.f16.f16.f32 "
        "{%0,%1,%2,%3}, {%4,%5,%6,%7}, {%8,%9}, {%0,%1,%2,%3};"
        : "+f"(c[0]), "+f"(c[1]), "+f"(c[2]), "+f"(c[3])
        : "r"(a[0]), "r"(a[1]), "r"(a[2]), "r"(a[3]), "r"(b[0]), "r"(b[1]));
}
__device__ __forceinline__ void cp16(uint32_t dst, const void* src) {
    asm volatile("cp.async.cg.shared.global [%0], [%1], 16;" :: "r"(dst), "l"(src));
}
__device__ __forceinline__ void cp_commit() {
    asm volatile("cp.async.commit_group;" ::: "memory");
}
__device__ __forceinline__ void cp_wait0() {
    asm volatile("cp.async.wait_group 0;" ::: "memory");
}
__device__ __forceinline__ void cp_wait1() {
    asm volatile("cp.async.wait_group 1;" ::: "memory");
}
__device__ __forceinline__ void cp_wait2() {
    asm volatile("cp.async.wait_group 2;" ::: "memory");
}

// load ROWS x 64 fp16 tile into SW128-swizzled smem via cp.async
template <int ROWS, int THREADS>
__device__ __forceinline__ void load_tile(uint32_t sdst, const __half* g,
                                          int ld, int tid) {
#pragma unroll
    for (int i = 0; i < ROWS * 8 / THREADS; ++i) {
        int idx = i * THREADS + tid;
        int row = idx >> 3, ch = idx & 7;
        uint32_t dst = sdst + row * 128 + ((ch * 16) ^ ((row & 7) << 4));
        cp16(dst, g + (size_t)row * ld + ch * 8);
    }
}

// one K-chunk (64) of single-pass fp16 mma: acc += A*B
template <int MT, int NT>
__device__ __forceinline__ void compute_chunk1(uint32_t sA, uint32_t sB,
                                               int warpRow, int warpCol, int lane,
                                               float (&acc)[MT][NT][4]) {
    int mi = lane >> 3;
    int arow = warpRow + ((mi & 1) << 3) + (lane & 7);
    uint32_t axor = (uint32_t)((arow & 7) << 4);
    uint32_t aoff = (uint32_t)arow * 128;
    int akb = (mi >> 1) << 4;
    int brow = warpCol + (lane & 7);
    int bi = (lane >> 3) & 1;
    uint32_t bxor = (uint32_t)((brow & 7) << 4);
    uint32_t boff = (uint32_t)brow * 128;
    int bkb = bi << 4;
#pragma unroll
    for (int ks = 0; ks < 4; ++ks) {
        uint32_t af[MT][4], bh[NT][2];
        uint32_t ak = (uint32_t)((ks * 32 + akb) ^ axor);
        uint32_t bk = (uint32_t)((ks * 32 + bkb) ^ bxor);
#pragma unroll
        for (int i = 0; i < MT; ++i) ldsm_x4(af[i], sA + aoff + i * 2048 + ak);
#pragma unroll
        for (int j = 0; j < NT; ++j) ldsm_x2(bh[j], sB + boff + j * 1024 + bk);
#pragma unroll
        for (int i = 0; i < MT; ++i)
#pragma unroll
            for (int j = 0; j < NT; ++j) mma_f16(acc[i][j], af[i], bh[j]);
    }
}

// ---------------- kernel: fp32 -> fp16 conversions (all weights) -------------
#define N_W (FDIM * DDIM / 4)
#define N_A1 (NEXP * RLORA * DDIM / 4)
#define N_A2 (NEXP * RLORA * FDIM / 4)
__global__ void cvt_kernel(const float* __restrict__ w1, const float* __restrict__ w3,
                           const float* __restrict__ w2, const float* __restrict__ a1,
                           const float* __restrict__ a3, const float* __restrict__ a2) {
    const int total = 3 * N_W + 2 * N_A1 + N_A2;
    for (int i = blockIdx.x * blockDim.x + threadIdx.x; i < total;
         i += gridDim.x * blockDim.x) {
        int j = i;
        const float4* s;
        uint2* d;
        if (j < N_W)                    { s = (const float4*)w1; d = (uint2*)g_w1h; }
        else if ((j -= N_W) < N_W)      { s = (const float4*)w3; d = (uint2*)g_w3h; }
        else if ((j -= N_W) < N_W)      { s = (const float4*)w2; d = (uint2*)g_w2h; }
        else if ((j -= N_W) < N_A1)     { s = (const float4*)a1; d = (uint2*)g_aUh; }
        else if ((j -= N_A1) < N_A1)    { s = (const float4*)a3;
                                          d = (uint2*)(g_aUh + NEXP * RLORA * DDIM); }
        else { j -= N_A1;                 s = (const float4*)a2; d = (uint2*)g_a2h; }
        float4 v = s[j];
        uint2 o;
        o.x = packh(v.x, v.y);
        o.y = packh(v.z, v.w);
        d[j] = o;
    }
}

// ---------------- kernel: fused RMSNorm + router (+ etr2 zero) ---------------
__global__ void rmsnorm_router_kernel(const float* __restrict__ x,
                                      const float* __restrict__ nw,
                                      const float* __restrict__ gw) {
    int tok = blockIdx.x;
    int tid = threadIdx.x;
    if (tid < 32) g_etr2[tok * 32 + tid] = 0.f;
    float4 v = ((const float4*)(x + (size_t)tok * DDIM))[tid];
    float ss = v.x * v.x + v.y * v.y + v.z * v.z + v.w * v.w;
#pragma unroll
    for (int o = 16; o; o >>= 1) ss += __shfl_xor_sync(0xffffffffu, ss, o);
    __shared__ float red[8];
    if ((tid & 31) == 0) red[tid >> 5] = ss;
    __syncthreads();
    float tot = 0.f;
#pragma unroll
    for (int i = 0; i < 8; ++i) tot += red[i];
    float sc = rsqrtf(tot / (float)DDIM + EPS_RMS);
    float4 w = ((const float4*)nw)[tid];
    float4 o = make_float4(v.x * sc * w.x, v.y * sc * w.y, v.z * sc * w.z,
                           v.w * sc * w.w);
    ((float4*)(g_t + (size_t)tok * DDIM))[tid] = o;
    uint2 h;
    h.x = packh(o.x, o.y);
    h.y = packh(o.z, o.w);
    ((uint2*)g_th)[tok * 256 + tid] = h;

    float r[NEXP];
#pragma unroll
    for (int e = 0; e < NEXP; ++e) {
        float4 gv = ((const float4*)gw)[e * 256 + tid];
        r[e] = o.x * gv.x + o.y * gv.y + o.z * gv.z + o.w * gv.w;
    }
#pragma unroll
    for (int e = 0; e < NEXP; ++e) {
#pragma unroll
        for (int off = 16; off; off >>= 1)
            r[e] += __shfl_xor_sync(0xffffffffu, r[e], off);
    }
    __shared__ float lg[8][NEXP];
    if ((tid & 31) == 0) {
#pragma unroll
        for (int e = 0; e < NEXP; ++e) lg[tid >> 5][e] = r[e];
    }
    __syncthreads();
    if (tid == 0) {
        float s8[NEXP];
#pragma unroll
        for (int e = 0; e < NEXP; ++e) {
            float t = 0.f;
#pragma unroll
            for (int wgi = 0; wgi < 8; ++wgi) t += lg[wgi][e];
            s8[e] = t;
        }
        int i0 = 0;
#pragma unroll
        for (int i = 1; i < NEXP; ++i) if (s8[i] > s8[i0]) i0 = i;
        int i1 = (i0 == 0) ? 1 : 0;
#pragma unroll
        for (int i = 0; i < NEXP; ++i) if (i != i0 && s8[i] > s8[i1]) i1 = i;
        float e1 = expf(s8[i1] - s8[i0]);
        float inv = 1.f / (1.f + e1);
        g_topi[tok * 2 + 0] = i0;
        g_topi[tok * 2 + 1] = i1;
        g_topw[tok * 2 + 0] = inv;
        g_topw[tok * 2 + 1] = e1 * inv;
    }
}

// ---------------- kernel: expert-sort pairs ----------------------------------
__global__ void sort_kernel() {
    __shared__ int cnt[NEXP], ofs[NEXP + 1], cur[NEXP];
    int tid = threadIdx.x;
    if (tid < NEXP) cnt[tid] = 0;
    __syncthreads();
    for (int p = tid; p < NPAIR; p += 256) atomicAdd(&cnt[g_topi[p]], 1);
    __syncthreads();
    if (tid == 0) {
        ofs[0] = 0;
        for (int e = 0; e < NEXP; ++e) { ofs[e + 1] = ofs[e] + cnt[e]; cur[e] = ofs[e]; }
        int ng = 0;
        for (int e = 0; e < NEXP; ++e)
            for (int s = 0; s < cnt[e]; s += GSZ) {
                g_gstart[ng] = ofs[e] + s;
                g_glen[ng] = min(GSZ, cnt[e] - s);
                g_gexp[ng] = e;
                ng++;
            }
        g_ngroups = ng;
    }
    __syncthreads();
    for (int p = tid; p < NPAIR; p += 256) {
        int pos = atomicAdd(&cur[g_topi[p]], 1);
        g_sorted[pos] = p;
    }
}

// ---------------- kernel: up GEMMs (128x128 tile, 1-pass fp16, 3 stages) -----
// mode: -1 -> blockIdx.z selects w1/w3; 2 -> dense LoRA-up (B=aU, dst=etrupd)
#define UP_TA (128 * 64 * 2)
#define UP_TB (128 * 64 * 2)
#define UP_STAGE (UP_TA + UP_TB)
__global__ __launch_bounds__(256, 2) void up_mma_kernel(int mode) {
    extern __shared__ __align__(128) char smem[];
    const int tid = threadIdx.x;
    const int wid = tid >> 5, lane = tid & 31;
    const int warpRow = (wid >> 1) * 32, warpCol = (wid & 1) * 64;
    uint32_t sb = smem_u32(smem);

    int sel = (mode < 0) ? (int)blockIdx.z : mode;
    const __half* Bbase;
    float* dst;
    int ldc;
    if (sel == 0)      { Bbase = g_w1h; dst = g_base1; ldc = FDIM; }
    else if (sel == 1) { Bbase = g_w3h; dst = g_base3; ldc = FDIM; }
    else               { Bbase = g_aUh; dst = g_etrupd; ldc = 256; }

    const __half* Ah = g_th + (size_t)blockIdx.y * 128 * DDIM;
    const __half* Bh = Bbase + (size_t)blockIdx.x * 128 * DDIM;

    float acc[2][8][4] = {};
    const int NC = DDIM / 64;  // 16

    {
        load_tile<128, 256>(sb, Ah, DDIM, tid);
        load_tile<128, 256>(sb + UP_TA, Bh, DDIM, tid);
        cp_commit();
        uint32_t s1 = sb + UP_STAGE;
        load_tile<128, 256>(s1, Ah + 64, DDIM, tid);
        load_tile<128, 256>(s1 + UP_TA, Bh + 64, DDIM, tid);
        cp_commit();
    }
    for (int c = 0; c < NC; ++c) {
        if (c + 2 < NC) {
            uint32_t s2 = sb + ((c + 2) % 3) * UP_STAGE;
            load_tile<128, 256>(s2, Ah + (c + 2) * 64, DDIM, tid);
            load_tile<128, 256>(s2 + UP_TA, Bh + (c + 2) * 64, DDIM, tid);
            cp_commit();
            cp_wait2();
        } else if (c + 1 < NC) {
            cp_wait1();
        } else {
            cp_wait0();
        }
        __syncthreads();
        uint32_t s = sb + (c % 3) * UP_STAGE;
        compute_chunk1<2, 8>(s, s + UP_TA, warpRow, warpCol, lane, acc);
        __syncthreads();
    }

    int grp = lane >> 2, q = lane & 3;
#pragma unroll
    for (int i = 0; i < 2; ++i) {
        int r0 = blockIdx.y * 128 + warpRow + i * 16 + grp;
#pragma unroll
        for (int j = 0; j < 8; ++j) {
            int col = blockIdx.x * 128 + warpCol + j * 8 + q * 2;
            *(float2*)(dst + (size_t)r0 * ldc + col) =
                make_float2(acc[i][j][0], acc[i][j][1]);
            *(float2*)(dst + (size_t)(r0 + 8) * ldc + col) =
                make_float2(acc[i][j][2], acc[i][j][3]);
        }
    }
}

// ---------------- kernel: grouped LoRA expand + SwiGLU (fp16 act) ------------
__global__ __launch_bounds__(256) void act_group_kernel(const float* __restrict__ b1w,
                                                        const float* __restrict__ b3w) {
    int gi = blockIdx.x;
    if (gi >= g_ngroups) return;
    int e = g_gexp[gi], start = g_gstart[gi], len = g_glen[gi];
    int tid = threadIdx.x;
    int f0 = blockIdx.y * 512 + tid * 2;
    __shared__ float sg[GSZ][32];
    __shared__ int sp[GSZ];
    for (int i = tid; i < len * 32; i += 256) {
        int k = i >> 5, j = i & 31;
        int p = g_sorted[start + k], tok = p >> 1;
        int col = (j < 16) ? (e * 16 + j) : (128 + e * 16 + (j - 16));
        sg[k][j] = g_etrupd[tok * 256 + col];
    }
    if (tid < len) sp[tid] = g_sorted[start + tid];
    __syncthreads();

    float b1r[2][16], b3r[2][16];
#pragma unroll
    for (int fi = 0; fi < 2; ++fi) {
        const float4* q1 = (const float4*)(b1w + ((size_t)e * FDIM + f0 + fi) * RLORA);
        const float4* q3 = (const float4*)(b3w + ((size_t)e * FDIM + f0 + fi) * RLORA);
#pragma unroll
        for (int i = 0; i < 4; ++i) {
            float4 v1 = q1[i], v3 = q3[i];
            b1r[fi][i * 4 + 0] = v1.x; b1r[fi][i * 4 + 1] = v1.y;
            b1r[fi][i * 4 + 2] = v1.z; b1r[fi][i * 4 + 3] = v1.w;
            b3r[fi][i * 4 + 0] = v3.x; b3r[fi][i * 4 + 1] = v3.y;
            b3r[fi][i * 4 + 2] = v3.z; b3r[fi][i * 4 + 3] = v3.w;
        }
    }
    for (int k = 0; k < len; ++k) {
        int p = sp[k], tok = p >> 1;
        float2 bs1 = *(const float2*)(g_base1 + (size_t)tok * FDIM + f0);
        float2 bs3 = *(const float2*)(g_base3 + (size_t)tok * FDIM + f0);
        float hv[2];
#pragma unroll
        for (int fi = 0; fi < 2; ++fi) {
            float l1 = 0.f, l3 = 0.f;
#pragma unroll
            for (int r = 0; r < 16; ++r) {
                l1 += b1r[fi][r] * sg[k][r];
                l3 += b3r[fi][r] * sg[k][16 + r];
            }
            float h1 = (fi ? bs1.y : bs1.x) + SCALING * l1;
            float h3 = (fi ? bs3.y : bs3.x) + SCALING * l3;
            hv[fi] = (h1 / (1.f + expf(-h1))) * h3;
        }
        ((uint32_t*)g_acth)[((size_t)p * FDIM + f0) >> 1] = packh(hv[0], hv[1]);
    }
}

// ---------------- kernel: grouped down LoRA rank projection ------------------
#define A2PITCH 516
__global__ __launch_bounds__(256) void etr2_group_kernel() {
    int gi = blockIdx.x;
    if (gi >= g_ngroups) return;
    int e = g_gexp[gi], start = g_gstart[gi], len = g_glen[gi];
    int cidx = blockIdx.y;
    int tid = threadIdx.x;
    extern __shared__ __align__(16) uint32_t sm[];
    uint32_t* sa2 = sm;                       // [16][A2PITCH]
    uint32_t* sact = sm + 16 * A2PITCH;       // [32][A2PITCH]
    __shared__ int sp[GSZ];
    if (tid < len) sp[tid] = g_sorted[start + tid];
    __syncthreads();
    const uint32_t* a2g = (const uint32_t*)g_a2h;
    for (int i = tid; i < 16 * 512; i += 256) {
        int r = i >> 9, d = i & 511;
        sa2[r * A2PITCH + d] = a2g[((size_t)(e * RLORA + r) << 11) + (cidx << 9) + d];
    }
    const uint32_t* actg = (const uint32_t*)g_acth;
    for (int i = tid; i < len * 512; i += 256) {
        int k = i >> 9, d = i & 511;
        sact[k * A2PITCH + d] = actg[((size_t)sp[k] << 11) + (cidx << 9) + d];
    }
    __syncthreads();
    int k = tid >> 3, rr = tid & 7;
    if (k < len) {
        float a0 = 0.f, a1 = 0.f;
        const uint32_t* ar = sact + k * A2PITCH;
        const uint32_t* b0 = sa2 + rr * A2PITCH;
        const uint32_t* b1 = sa2 + (rr + 8) * A2PITCH;
#pragma unroll 4
        for (int d = 0; d < 512; ++d) {
            float2 av = h22f2(ar[d]);
            float2 v0 = h22f2(b0[d]);
            float2 v1 = h22f2(b1[d]);
            a0 += av.x * v0.x + av.y * v0.y;
            a1 += av.x * v1.x + av.y * v1.y;
        }
        int p = sp[k];
        float sc = SCALING * g_topw[p];
        atomicAdd(&g_etr2[p * RLORA + rr], a0 * sc);
        atomicAdd(&g_etr2[p * RLORA + rr + 8], a1 * sc);
    }
}

// ---------------- kernel: weighted pair combine (single fp16) ----------------
__global__ void combine_kernel() {
    int tok = blockIdx.x;
    int f0 = (blockIdx.y * 256 + threadIdx.x) * 4;
    float w0 = g_topw[tok * 2], w1 = g_topw[tok * 2 + 1];
    size_t i0 = ((size_t)(2 * tok) * FDIM + f0) >> 2;
    size_t i1 = i0 + (FDIM >> 2);
    uint2 u0 = ((const uint2*)g_acth)[i0];
    uint2 u1 = ((const uint2*)g_acth)[i1];
    float2 a01 = h22f2(u0.x), a23 = h22f2(u0.y);
    float2 b01 = h22f2(u1.x), b23 = h22f2(u1.y);
    uint2 h;
    h.x = packh(w0 * a01.x + w1 * b01.x, w0 * a01.y + w1 * b01.y);
    h.y = packh(w0 * a23.x + w1 * b23.x, w0 * a23.y + w1 * b23.y);
    ((uint2*)g_ch)[((size_t)tok * FDIM + f0) >> 2] = h;
}

// ---------------- kernel: down GEMM (64x128, splitK=2, 1-pass, 3 stages) -----
#define DN_TA (64 * 64 * 2)
#define DN_TB (128 * 64 * 2)
#define DN_STAGE (DN_TA + DN_TB)
__global__ __launch_bounds__(256, 2) void down_mma_kernel(const float* __restrict__ B2,
                                                          float* __restrict__ Out) {
    extern __shared__ __align__(128) char smem[];
    const int tid = threadIdx.x;
    const int wid = tid >> 5, lane = tid & 31;
    const int warpRow = (wid >> 2) * 32, warpCol = (wid & 3) * 32;
    uint32_t sb = smem_u32(smem);
    const int kOff = blockIdx.z * (FDIM / 2);

    const __half* Ah = g_ch + (size_t)blockIdx.y * 64 * FDIM + kOff;
    const __half* Bh = g_w2h + (size_t)blockIdx.x * 128 * FDIM + kOff;

    float acc[2][4][4] = {};
    const int NC = (FDIM / 2) / 64;  // 32

    {
        load_tile<64, 256>(sb, Ah, FDIM, tid);
        load_tile<128, 256>(sb + DN_TA, Bh, FDIM, tid);
        cp_commit();
        uint32_t s1 = sb + DN_STAGE;
        load_tile<64, 256>(s1, Ah + 64, FDIM, tid);
        load_tile<128, 256>(s1 + DN_TA, Bh + 64, FDIM, tid);
        cp_commit();
    }
    for (int c = 0; c < NC; ++c) {
        if (c + 2 < NC) {
            uint32_t s2 = sb + ((c + 2) % 3) * DN_STAGE;
            load_tile<64, 256>(s2, Ah + (c + 2) * 64, FDIM, tid);
            load_tile<128, 256>(s2 + DN_TA, Bh + (c + 2) * 64, FDIM, tid);
            cp_commit();
            cp_wait2();
        } else if (c + 1 < NC) {
            cp_wait1();
        } else {
            cp_wait0();
        }
        __syncthreads();
        uint32_t s = sb + (c % 3) * DN_STAGE;
        compute_chunk1<2, 4>(s, s + DN_TA, warpRow, warpCol, lane, acc);
        __syncthreads();
    }

    int grp = lane >> 2, q = lane & 3;
#pragma unroll
    for (int i = 0; i < 2; ++i) {
#pragma unroll
        for (int half = 0; half < 2; ++half) {
            int t = blockIdx.y * 64 + warpRow + i * 16 + half * 8 + grp;
            if (blockIdx.z == 0) {
                int p0 = 2 * t, p1 = 2 * t + 1;
                int e0 = g_topi[p0], e1 = g_topi[p1];
                float er0[16], er1[16];
                const float4* q0 = (const float4*)(g_etr2 + p0 * RLORA);
                const float4* q1v = (const float4*)(g_etr2 + p1 * RLORA);
#pragma unroll
                for (int kk = 0; kk < 4; ++kk) {
                    float4 a = q0[kk], b = q1v[kk];
                    er0[kk * 4 + 0] = a.x; er0[kk * 4 + 1] = a.y;
                    er0[kk * 4 + 2] = a.z; er0[kk * 4 + 3] = a.w;
                    er1[kk * 4 + 0] = b.x; er1[kk * 4 + 1] = b.y;
                    er1[kk * 4 + 2] = b.z; er1[kk * 4 + 3] = b.w;
                }
#pragma unroll
                for (int j = 0; j < 4; ++j) {
#pragma unroll
                    for (int c2 = 0; c2 < 2; ++c2) {
                        int d = blockIdx.x * 128 + warpCol + j * 8 + q * 2 + c2;
                        const float4* r0p =
                            (const float4*)(B2 + ((size_t)e0 * DDIM + d) * RLORA);
                        const float4* r1p =
                            (const float4*)(B2 + ((size_t)e1 * DDIM + d) * RLORA);
                        float dot = 0.f;
#pragma unroll
                        for (int kk = 0; kk < 4; ++kk) {
                            float4 b0 = r0p[kk], b1v = r1p[kk];
                            dot += b0.x * er0[kk * 4 + 0] + b0.y * er0[kk * 4 + 1] +
                                   b0.z * er0[kk * 4 + 2] + b0.w * er0[kk * 4 + 3];
                            dot += b1v.x * er1[kk * 4 + 0] + b1v.y * er1[kk * 4 + 1] +
                                   b1v.z * er1[kk * 4 + 2] + b1v.w * er1[kk * 4 + 3];
                        }
                        atomicAdd(&Out[(size_t)t * DDIM + d],
                                  acc[i][j][half * 2 + c2] + dot);
                    }
                }
            } else {
#pragma unroll
                for (int j = 0; j < 4; ++j) {
#pragma unroll
                    for (int c2 = 0; c2 < 2; ++c2) {
                        int d = blockIdx.x * 128 + warpCol + j * 8 + q * 2 + c2;
                        atomicAdd(&Out[(size_t)t * DDIM + d], acc[i][j][half * 2 + c2]);
                    }
                }
            }
        }
    }
}

// ---------------- launcher ---------------------------------------------------
extern "C" void kernel_launch(void* const* d_in, const int* in_sizes, int n_in,
                              void* d_out, int out_size) {
    const float* x      = (const float*)d_in[0];
    const float* norm_w = (const float*)d_in[1];
    const float* w1     = (const float*)d_in[2];
    const float* w3     = (const float*)d_in[3];
    const float* w2     = (const float*)d_in[4];
    const float* gate_w = (const float*)d_in[5];
    const float* a1     = (const float*)d_in[6];
    const float* b1     = (const float*)d_in[7];
    const float* a3     = (const float*)d_in[8];
    const float* b3     = (const float*)d_in[9];
    const float* a2     = (const float*)d_in[10];
    const float* b2     = (const float*)d_in[11];
    float* out = (float*)d_out;

    const int ETR2_SMEM = (16 + 32) * A2PITCH * 4;   // 99072
    cudaFuncSetAttribute(up_mma_kernel,
                         cudaFuncAttributeMaxDynamicSharedMemorySize, 3 * UP_STAGE);
    cudaFuncSetAttribute(down_mma_kernel,
                         cudaFuncAttributeMaxDynamicSharedMemorySize, 3 * DN_STAGE);
    cudaFuncSetAttribute(etr2_group_kernel,
                         cudaFuncAttributeMaxDynamicSharedMemorySize, ETR2_SMEM);

    cudaMemsetAsync(d_out, 0, (size_t)out_size * sizeof(float));
    cvt_kernel<<<1024, 256>>>(w1, w3, w2, a1, a3, a2);
    rmsnorm_router_kernel<<<T_TOK, 256>>>(x, norm_w, gate_w);
    sort_kernel<<<1, 256>>>();
    up_mma_kernel<<<dim3(FDIM / 128, T_TOK / 128, 2), 256, 3 * UP_STAGE>>>(-1);
    up_mma_kernel<<<dim3(2, T_TOK / 128), 256, 3 * UP_STAGE>>>(2);  // dense LoRA-up
    act_group_kernel<<<dim3(MAXG, 8), 256>>>(b1, b3);
    etr2_group_kernel<<<dim3(MAXG, 4), 256, ETR2_SMEM>>>();
    combine_kernel<<<dim3(T_TOK, 4), 256>>>();
    down_mma_kernel<<<dim3(DDIM / 128, T_TOK / 64, 2), 256, 3 * DN_STAGE>>>(b2, out);
}